// round 10
// baseline (speedup 1.0000x reference)
#include <cuda_runtime.h>
#include <math.h>

#define NMODES   6400
#define MDIM     80
#define NCHUNK   64
#define CHUNK    (NMODES / NCHUNK)      /* 100 modes per chunk */
#define MAX_T    24576
#define TW       32                      /* samples per thread, stride 32 */
#define SPAN     1024                    /* samples per warp tile */
#define WPB      4                       /* warps per block in k1 */

#define KF   ((float)(1.0 / 44100.0))
#define K2F  ((float)((1.0/44100.0)*(1.0/44100.0)))

__device__ float    g_part[NCHUNK][MAX_T];
__device__ unsigned g_maxbits;
__device__ unsigned g_bar;

// ---------------------------------------------------------------------------
// Accurate flag-proof float sine / sincos / cosine (Cody-Waite, minimax).
// ---------------------------------------------------------------------------
__device__ __forceinline__ float sin_acc(float x) {
    const float INV_PI = 0.318309886183790671538f;
    float nf = rintf(__fmul_rn(x, INV_PI));
    int   ni = (int)nf;
    float r = __fmaf_rn(-nf, 3.140625f, x);
    r = __fmaf_rn(-nf, 9.670257568359375e-4f, r);
    r = __fmaf_rn(-nf, 6.2771141529083252e-7f, r);
    float r2 = __fmul_rn(r, r);
    float p  = __fmaf_rn(2.60831598097865935e-06f, r2, -1.98106907191686332e-4f);
    p = __fmaf_rn(p, r2,  8.33307858556509018e-3f);
    p = __fmaf_rn(p, r2, -0.166666597127914429f);
    float s = __fmaf_rn(__fmul_rn(r, r2), p, r);
    return __int_as_float(__float_as_int(s) ^ ((ni & 1) << 31));
}

__device__ __forceinline__ void sincos_acc(float x, float& so, float& co) {
    const float INV_PI = 0.318309886183790671538f;
    float nf = rintf(__fmul_rn(x, INV_PI));
    int   sgn = ((int)nf & 1) << 31;
    float r = __fmaf_rn(-nf, 3.140625f, x);
    r = __fmaf_rn(-nf, 9.670257568359375e-4f, r);
    r = __fmaf_rn(-nf, 6.2771141529083252e-7f, r);
    float r2 = __fmul_rn(r, r);
    float ps = __fmaf_rn(2.60831598097865935e-06f, r2, -1.98106907191686332e-4f);
    ps = __fmaf_rn(ps, r2,  8.33307858556509018e-3f);
    ps = __fmaf_rn(ps, r2, -0.166666597127914429f);
    float s = __fmaf_rn(__fmul_rn(r, r2), ps, r);
    float pc = __fmaf_rn(2.44331571e-5f, r2, -1.38873162e-3f);
    pc = __fmaf_rn(pc, r2, 4.16666456e-2f);
    pc = __fmaf_rn(pc, r2, -0.5f);
    float c = __fmaf_rn(pc, r2, 1.0f);
    so = __int_as_float(__float_as_int(s) ^ sgn);
    co = __int_as_float(__float_as_int(c) ^ sgn);
}

// cos(x) for amplitude path, |x| < ~400
__device__ __forceinline__ float cos_accf(float x) {
    const float INV_PI = 0.318309886183790671538f;
    float nf = rintf(__fmaf_rn(x, INV_PI, -0.5f));
    int   ni = (int)nf;
    float nh = __fadd_rn(nf, 0.5f);
    float r = __fmaf_rn(-nh, 3.140625f, x);
    r = __fmaf_rn(-nh, 9.670257568359375e-4f, r);
    r = __fmaf_rn(-nh, 6.2771141529083252e-7f, r);
    r = __fmaf_rn(-nh, 1.2154201256553420e-10f, r);
    float r2 = __fmul_rn(r, r);
    float p  = __fmaf_rn(2.60831598097865935e-06f, r2, -1.98106907191686332e-4f);
    p = __fmaf_rn(p, r2,  8.33307858556509018e-3f);
    p = __fmaf_rn(p, r2, -0.166666597127914429f);
    float s = __fmaf_rn(__fmul_rn(r, r2), p, r);
    return __int_as_float(__float_as_int(s) ^ ((~ni & 1) << 31));
}

// ---------------------------------------------------------------------------
// Short custom double transcendentals (branch-free, known small ranges).
// ---------------------------------------------------------------------------
__device__ __forceinline__ void sincos_d(double x, double& so, double& co) {
    double n = rint(x * 0.31830988618379067154);
    double r = fma(-n, 3.14159265358979311600, x);
    double y = r * r;
    double ps =        1.58969099521155010221e-10;
    ps = fma(ps, y, -2.50507602534068634195e-08);
    ps = fma(ps, y,  2.75573137070700676789e-06);
    ps = fma(ps, y, -1.98412698298579493134e-04);
    ps = fma(ps, y,  8.33333333332248946124e-03);
    ps = fma(ps, y, -1.66666666666666324348e-01);
    double s = fma(r * y, ps, r);
    double pc =       -1.13596475577881948265e-11;
    pc = fma(pc, y,  2.08757232129817482790e-09);
    pc = fma(pc, y, -2.75573143513906633035e-07);
    pc = fma(pc, y,  2.48015872894767294178e-05);
    pc = fma(pc, y, -1.38888888888741095749e-03);
    pc = fma(pc, y,  4.16666666666666019037e-02);
    double c = fma(y * y, pc, fma(y, -0.5, 1.0));
    long long ni = (long long)n;
    if (ni & 1) { s = -s; c = -c; }
    so = s; co = c;
}

// exp(v), v in [-745, 0]; branch-free (clamp guards the scale only)
__device__ __forceinline__ double exp_d(double v) {
    double vc = fmax(v, -700.0);
    double kd = rint(vc * 1.44269504088896340736);
    double r = fma(-kd, 6.93147180369123816490e-01, vc);
    r = fma(-kd, 1.90821492927058770002e-10, r);
    double p =       2.50521083854417187751e-08;
    p = fma(p, r, 2.75573192239858906526e-07);
    p = fma(p, r, 2.75573192239858925110e-06);
    p = fma(p, r, 2.48015873015873015873e-05);
    p = fma(p, r, 1.98412698412698412526e-04);
    p = fma(p, r, 1.38888888888888894069e-03);
    p = fma(p, r, 8.33333333333333321769e-03);
    p = fma(p, r, 4.16666666666666666435e-02);
    p = fma(p, r, 1.66666666666666666666e-01);
    p = fma(p, r, 5.00000000000000000000e-01);
    p = fma(p, r, 1.0);
    p = fma(p, r, 1.0);
    long long ki = (long long)kd;
    double two_k = __longlong_as_double((1023LL + ki) << 52);
    return p * two_k;
}

// log1p(e) for e in (0, 1]; branch-free select reduction + atanh series.
__device__ __forceinline__ double log1p_d(double e) {
    double w = 1.0 + e;
    bool   big = w > 1.4142135623730951;
    double m   = big ? 0.5 * w : w;
    double kln = big ? 6.93147180559945309417e-01 : 0.0;
    double s = (m - 1.0) / (m + 1.0);
    double z = s * s;
    double q =      6.66666666666666666667e-02;
    q = fma(q, z, 7.69230769230769230769e-02);
    q = fma(q, z, 9.09090909090909090909e-02);
    q = fma(q, z, 1.11111111111111111111e-01);
    q = fma(q, z, 1.42857142857142857143e-01);
    q = fma(q, z, 2.00000000000000000000e-01);
    q = fma(q, z, 3.33333333333333333333e-01);
    double at = fma(s * z, q, s);
    return fma(2.0, at, kln);
}

__device__ __forceinline__ float sigmoid_f(float x) {
    return __fdiv_rn(1.0f, __fadd_rn(1.0f, __expf(-x)));
}

// ---------------------------------------------------------------------------
// k1: fused setup + modal bank. Each block computes its own chunk's 100 mode
// params into SHARED (threads 0-5: scalar transforms; threads 0-99: one mode
// each — identical arithmetic to the old k0, so tables are bit-identical),
// then runs the round-4 recurrence main loop reading params via LDS.
// ---------------------------------------------------------------------------
__global__ void __launch_bounds__(32 * WPB) k1_bank(
        int T,
        const float* __restrict__ mu_raw,  const float* __restrict__ D_raw,
        const float* __restrict__ T0_raw,  const float* __restrict__ Ly_raw,
        const float* __restrict__ xo_raw,  const float* __restrict__ yo_raw) {
    __shared__ float  sc[6];
    __shared__ float4 sP0[CHUNK];
    __shared__ float4 sP1[CHUNK];
    __shared__ float  sP2[CHUNK];

    int tid = threadIdx.x;
    int c   = blockIdx.y;

    // reset tail-kernel state (every block writes the same values; k2 runs
    // strictly after k1, so no ordering hazard)
    if (tid == 0 && blockIdx.x == 0) { g_maxbits = 0u; g_bar = 0u; }

    // ---- phase A: scalar input transforms (lanes 0-5, uniform path) ----
    if (tid < 6) {
        const float* p = (tid == 0) ? mu_raw : (tid == 1) ? D_raw :
                         (tid == 2) ? T0_raw : (tid == 3) ? Ly_raw :
                         (tid == 4) ? xo_raw : yo_raw;
        double x  = (double)*p;
        double ax = fabs(x);
        double sp = fmax(x, 0.0) + log1p_d(exp_d(-ax));
        double et = exp_d(-2.0 * ax);
        double th = (1.0 - et) / (1.0 + et);
        th = (x < 0.0) ? -th : th;
        float r = (tid < 3) ? __fadd_rn((float)sp, 1e-4f)
                            : __fmul_rn(__fadd_rn((float)th, 1.0f), 0.5f);
        sc[tid] = r;
    }
    __syncthreads();

    // ---- phase B: per-mode params for this block's chunk (threads 0-99) ----
    if (tid < CHUNK) {
        int m = c * CHUNK + tid;
        float mu = sc[0], Dm = sc[1], T0m = sc[2];
        float Ly = __fadd_rn(1.1f, __fmul_rn(2.9f, sc[3]));
        float xo = __fadd_rn(0.49f, __fmul_rn(0.51f, sc[4]));
        float hy = sc[5];
        float yo = __fadd_rn(__fmul_rn(0.51f, Ly), __fmul_rn(__fmul_rn(0.49f, Ly), hy));
        float yi = __fmul_rn(0.467f, Ly);

        int mi = m / MDIM + 1;
        int nj = m % MDIM + 1;
        const float PIf = (float)M_PI;

        float mf = (float)mi, nf = (float)nj;
        float t1 = __fmul_rn(mf, PIf);
        float t2 = __fdiv_rn(__fmul_rn(nf, PIf), Ly);
        float g1 = __fadd_rn(__fmul_rn(t1, t1), __fmul_rn(t2, t2));
        float om_sq = __fadd_rn(__fmul_rn(T0m, g1),
                                __fmul_rn(__fmul_rn(Dm, g1), g1));
        float omega = __fsqrt_rn(fmaxf(om_sq, 0.0f));
        float theta = __fmul_rn(omega, KF);

        const double OM2d   = 2.0 * M_PI * 500.0;
        const double DOMSQd = OM2d * OM2d;
        const double ALPHAd = 3.0 * log(10.0) / DOMSQd * (DOMSQd / 6.0);
        const double BETAd  = 3.0 * log(10.0) / DOMSQd * (1.0 / 2.0 - 1.0 / 6.0);
        float om2f  = __fmul_rn(omega, omega);
        float sigma = __fadd_rn((float)ALPHAd, __fmul_rn((float)BETAd, om2f));

        const float MAXOMf = (float)(10000.0 * 2.0 * M_PI);
        const float LOWOMf = (float)(20.0 * 2.0 * M_PI);
        float a1 = __fdiv_rn(__fsub_rn(MAXOMf, omega), 100.0f);
        float a2 = __fdiv_rn(__fsub_rn(omega, LOWOMf), 100.0f);
        float valid = __fmul_rn(sigmoid_f(a1), sigmoid_f(a2));

        const float XIPI = (float)(0.335 * M_PI);
        float inw = __fmul_rn(cos_accf(__fmul_rn(XIPI, mf)),
                              cos_accf(__fdiv_rn(__fmul_rn(__fmul_rn(yi, PIf), nf), Ly)));
        float outw = __fmul_rn(cos_accf(__fmul_rn(__fmul_rn(xo, PIf), mf)),
                               cos_accf(__fdiv_rn(__fmul_rn(__fmul_rn(yo, PIf), nf), Ly)));

        float ms = __fmul_rn(__fmul_rn(0.25f, mu), Ly);
        float E  = __expf(-__fmul_rn(sigma, KF));
        float P  = __fmul_rn(outw, inw);
        P = __fmul_rn(P, K2F);
        P = __fmul_rn(P, E);
        P = __fdiv_rn(P, ms);
        P = __fmul_rn(P, valid);

        float coef = __fdiv_rn(P, __fadd_rn(sin_acc(theta), 1e-8f));

        double Th32 = 32.0 * (double)theta;
        double c32d, s32d;
        sincos_d(Th32, s32d, c32d);
        double r32d = exp_d(-32.0 * (double)sigma * (1.0 / 44100.0));
        float  a    = (float)(2.0 * r32d * c32d);
        float  b    = (float)(-(r32d * r32d));
        float  z1c  = (float)(r32d * c32d);
        float  z1s  = (float)(r32d * s32d);

        double zr = r32d * c32d, zi = r32d * s32d;
#pragma unroll
        for (int k = 0; k < 4; ++k) {
            double nzr = zr * zr - zi * zi;
            double nzi = 2.0 * zr * zi;
            zr = nzr; zi = nzi;
        }

        sP0[tid] = make_float4(theta, sigma, coef, a);
        sP1[tid] = make_float4(b, z1c, z1s, (float)zr);
        sP2[tid] = (float)zi;
    }
    __syncthreads();

    // ---- phase C: main loop (round-4 form, params from shared) ----
    int gtid   = blockIdx.x * blockDim.x + tid;
    int warp_t = gtid >> 5;
    int lane   = tid & 31;
    int base   = warp_t * SPAN + lane;
    if (base >= T) return;

    float acc[TW];
#pragma unroll
    for (int j = 0; j < TW; ++j) acc[j] = 0.0f;

    float tp0 = (float)(base + 1);
    float nk0 = __fmul_rn((float)base, KF);

    float4 nP0 = sP0[0];
    float4 nP1 = sP1[0];
    float  nP2 = sP2[0];

    for (int q = 0; q < CHUNK; ++q) {
        float4 p0 = nP0; float4 p1 = nP1; float p2 = nP2;
        if (q + 1 < CHUNK) {
            nP0 = sP0[q + 1];
            nP1 = sP1[q + 1];
            nP2 = sP2[q + 1];
        }
        float th = p0.x, sg = p0.y, C = p0.z, a = p0.w;
        float b = p1.x, z1c = p1.y, z1s = p1.z, Z16c = p1.w, Z16s = p2;

        float s0, c0;
        sincos_acc(__fmul_rn(tp0, th), s0, c0);
        float E   = __fmul_rn(C, __expf(-__fmul_rn(sg, nk0)));
        float Wim = __fmul_rn(E, s0);
        float Wre = __fmul_rn(E, c0);

        float v0 = Wim;
        float v1 = __fmaf_rn(Wre, z1s, __fmul_rn(Wim, z1c));
        acc[0] = __fadd_rn(acc[0], v0);
        acc[1] = __fadd_rn(acc[1], v1);
#pragma unroll
        for (int j = 2; j < 16; ++j) {
            float v2 = __fmaf_rn(a, v1, __fmul_rn(b, v0));
            acc[j] = __fadd_rn(acc[j], v2);
            v0 = v1; v1 = v2;
        }

        float Wre2 = __fmaf_rn(Wre, Z16c, -__fmul_rn(Wim, Z16s));
        float Wim2 = __fmaf_rn(Wim, Z16c,  __fmul_rn(Wre, Z16s));
        v0 = Wim2;
        v1 = __fmaf_rn(Wre2, z1s, __fmul_rn(Wim2, z1c));
        acc[16] = __fadd_rn(acc[16], v0);
        acc[17] = __fadd_rn(acc[17], v1);
#pragma unroll
        for (int j = 18; j < TW; ++j) {
            float v2 = __fmaf_rn(a, v1, __fmul_rn(b, v0));
            acc[j] = __fadd_rn(acc[j], v2);
            v0 = v1; v1 = v2;
        }
    }

#pragma unroll
    for (int j = 0; j < TW; ++j) {
        int t = base + 32 * j;
        if (t < T) g_part[c][t] = acc[j];
    }
}

// ---------------------------------------------------------------------------
// k2: fused diff + max + normalize (software grid barrier; 87 blocks < 148
// SMs -> all co-resident -> safe).
// ---------------------------------------------------------------------------
__global__ void k2_fused(int T, float* __restrict__ out) {
    __shared__ float sm[257];
    int t = blockIdx.x * blockDim.x + threadIdx.x;

    float s = 0.0f;
    if (t < T) {
#pragma unroll 8
        for (int c = 0; c < NCHUNK; ++c) s += g_part[c][t];
    }
    sm[threadIdx.x + 1] = s;
    if (threadIdx.x == 0) {
        float p = 0.0f;
        int tp = (int)(blockIdx.x * blockDim.x) - 1;
        if (tp >= 0 && tp < T) {
            for (int c = 0; c < NCHUNK; ++c) p += g_part[c][tp];
        }
        sm[0] = p;
    }
    __syncthreads();

    float ir = 0.0f;
    if (t < T) {
        float prev = (t == 0) ? 0.0f : sm[threadIdx.x];
        ir = __fdiv_rn(__fsub_rn(s, prev), KF);
        atomicMax(&g_maxbits, __float_as_uint(fabsf(ir)));
    }

    // ---- grid barrier ----
    __threadfence();
    __syncthreads();
    if (threadIdx.x == 0) {
        atomicAdd(&g_bar, 1u);
        while (*(volatile unsigned*)&g_bar < gridDim.x) {
            __nanosleep(64);
        }
    }
    __syncthreads();
    __threadfence();

    if (t < T) {
        float mx = __uint_as_float(*(volatile unsigned*)&g_maxbits);
        out[t] = __fdiv_rn(ir, __fadd_rn(mx, 1e-8f));
    }
}

// ---------------------------------------------------------------------------
extern "C" void kernel_launch(void* const* d_in, const int* in_sizes, int n_in,
                              void* d_out, int out_size) {
    (void)in_sizes; (void)n_in;
    const float* mu   = (const float*)d_in[0];
    const float* Dr   = (const float*)d_in[1];
    const float* T0r  = (const float*)d_in[2];
    const float* Lyr  = (const float*)d_in[3];
    const float* xor_ = (const float*)d_in[4];
    const float* yor_ = (const float*)d_in[5];

    int T = out_size;
    if (T > MAX_T) T = MAX_T;

    int warps_t  = (T + SPAN - 1) / SPAN;
    int blocks_x = (warps_t + WPB - 1) / WPB;
    dim3 g1(blocks_x, NCHUNK);
    k1_bank<<<g1, 32 * WPB>>>(T, mu, Dr, T0r, Lyr, xor_, yor_);

    int gb = (T + 255) / 256;
    k2_fused<<<gb, 256>>>(T, (float*)d_out);
}

// round 11
// speedup vs baseline: 1.0381x; 1.0381x over previous
#include <cuda_runtime.h>
#include <math.h>

#define NMODES   6400
#define MDIM     80
#define NCHUNK   64
#define CHUNK    (NMODES / NCHUNK)      /* 100 modes per chunk */
#define MAX_T    24576
#define TW       32                      /* samples per thread, stride 32 */
#define SPAN     1024                    /* samples per warp tile */
#define WPB      4                       /* warps per block in k1 */

#define KF   ((float)(1.0 / 44100.0))
#define K2F  ((float)((1.0/44100.0)*(1.0/44100.0)))

// per-mode tables
__device__ float4   g_P0[NMODES];   // {theta, sigma, C, a}
__device__ float4   g_P1[NMODES];   // {b, z1c, z1s, Z16c}
__device__ float    g_P2[NMODES];   // {Z16s}
__device__ float    g_part[NCHUNK][MAX_T];
__device__ unsigned g_maxbits;
__device__ unsigned g_bar;

// ---------------------------------------------------------------------------
// Accurate flag-proof float sine / sincos / cosine (Cody-Waite, minimax).
// ---------------------------------------------------------------------------
__device__ __forceinline__ float sin_acc(float x) {
    const float INV_PI = 0.318309886183790671538f;
    float nf = rintf(__fmul_rn(x, INV_PI));
    int   ni = (int)nf;
    float r = __fmaf_rn(-nf, 3.140625f, x);
    r = __fmaf_rn(-nf, 9.670257568359375e-4f, r);
    r = __fmaf_rn(-nf, 6.2771141529083252e-7f, r);
    float r2 = __fmul_rn(r, r);
    float p  = __fmaf_rn(2.60831598097865935e-06f, r2, -1.98106907191686332e-4f);
    p = __fmaf_rn(p, r2,  8.33307858556509018e-3f);
    p = __fmaf_rn(p, r2, -0.166666597127914429f);
    float s = __fmaf_rn(__fmul_rn(r, r2), p, r);
    return __int_as_float(__float_as_int(s) ^ ((ni & 1) << 31));
}

__device__ __forceinline__ void sincos_acc(float x, float& so, float& co) {
    const float INV_PI = 0.318309886183790671538f;
    float nf = rintf(__fmul_rn(x, INV_PI));
    int   sgn = ((int)nf & 1) << 31;
    float r = __fmaf_rn(-nf, 3.140625f, x);
    r = __fmaf_rn(-nf, 9.670257568359375e-4f, r);
    r = __fmaf_rn(-nf, 6.2771141529083252e-7f, r);
    float r2 = __fmul_rn(r, r);
    float ps = __fmaf_rn(2.60831598097865935e-06f, r2, -1.98106907191686332e-4f);
    ps = __fmaf_rn(ps, r2,  8.33307858556509018e-3f);
    ps = __fmaf_rn(ps, r2, -0.166666597127914429f);
    float s = __fmaf_rn(__fmul_rn(r, r2), ps, r);
    float pc = __fmaf_rn(2.44331571e-5f, r2, -1.38873162e-3f);
    pc = __fmaf_rn(pc, r2, 4.16666456e-2f);
    pc = __fmaf_rn(pc, r2, -0.5f);
    float c = __fmaf_rn(pc, r2, 1.0f);
    so = __int_as_float(__float_as_int(s) ^ sgn);
    co = __int_as_float(__float_as_int(c) ^ sgn);
}

// cos(x) for amplitude path, |x| < ~400
__device__ __forceinline__ float cos_accf(float x) {
    const float INV_PI = 0.318309886183790671538f;
    float nf = rintf(__fmaf_rn(x, INV_PI, -0.5f));
    int   ni = (int)nf;
    float nh = __fadd_rn(nf, 0.5f);
    float r = __fmaf_rn(-nh, 3.140625f, x);
    r = __fmaf_rn(-nh, 9.670257568359375e-4f, r);
    r = __fmaf_rn(-nh, 6.2771141529083252e-7f, r);
    r = __fmaf_rn(-nh, 1.2154201256553420e-10f, r);
    float r2 = __fmul_rn(r, r);
    float p  = __fmaf_rn(2.60831598097865935e-06f, r2, -1.98106907191686332e-4f);
    p = __fmaf_rn(p, r2,  8.33307858556509018e-3f);
    p = __fmaf_rn(p, r2, -0.166666597127914429f);
    float s = __fmaf_rn(__fmul_rn(r, r2), p, r);
    return __int_as_float(__float_as_int(s) ^ ((~ni & 1) << 31));
}

// ---------------------------------------------------------------------------
// Short custom double transcendentals (branch-free, known small ranges).
// ---------------------------------------------------------------------------
__device__ __forceinline__ void sincos_d(double x, double& so, double& co) {
    double n = rint(x * 0.31830988618379067154);
    double r = fma(-n, 3.14159265358979311600, x);
    double y = r * r;
    double ps =        1.58969099521155010221e-10;
    ps = fma(ps, y, -2.50507602534068634195e-08);
    ps = fma(ps, y,  2.75573137070700676789e-06);
    ps = fma(ps, y, -1.98412698298579493134e-04);
    ps = fma(ps, y,  8.33333333332248946124e-03);
    ps = fma(ps, y, -1.66666666666666324348e-01);
    double s = fma(r * y, ps, r);
    double pc =       -1.13596475577881948265e-11;
    pc = fma(pc, y,  2.08757232129817482790e-09);
    pc = fma(pc, y, -2.75573143513906633035e-07);
    pc = fma(pc, y,  2.48015872894767294178e-05);
    pc = fma(pc, y, -1.38888888888741095749e-03);
    pc = fma(pc, y,  4.16666666666666019037e-02);
    double c = fma(y * y, pc, fma(y, -0.5, 1.0));
    long long ni = (long long)n;
    if (ni & 1) { s = -s; c = -c; }
    so = s; co = c;
}

// exp(v), v in [-745, 0]; branch-free (clamp guards the scale only)
__device__ __forceinline__ double exp_d(double v) {
    double vc = fmax(v, -700.0);
    double kd = rint(vc * 1.44269504088896340736);
    double r = fma(-kd, 6.93147180369123816490e-01, vc);
    r = fma(-kd, 1.90821492927058770002e-10, r);
    double p =       2.50521083854417187751e-08;
    p = fma(p, r, 2.75573192239858906526e-07);
    p = fma(p, r, 2.75573192239858925110e-06);
    p = fma(p, r, 2.48015873015873015873e-05);
    p = fma(p, r, 1.98412698412698412526e-04);
    p = fma(p, r, 1.38888888888888894069e-03);
    p = fma(p, r, 8.33333333333333321769e-03);
    p = fma(p, r, 4.16666666666666666435e-02);
    p = fma(p, r, 1.66666666666666666666e-01);
    p = fma(p, r, 5.00000000000000000000e-01);
    p = fma(p, r, 1.0);
    p = fma(p, r, 1.0);
    long long ki = (long long)kd;
    double two_k = __longlong_as_double((1023LL + ki) << 52);
    return p * two_k;
}

// log1p(e) for e in (0, 1]; branch-free select reduction + atanh series.
__device__ __forceinline__ double log1p_d(double e) {
    double w = 1.0 + e;
    bool   big = w > 1.4142135623730951;
    double m   = big ? 0.5 * w : w;
    double kln = big ? 6.93147180559945309417e-01 : 0.0;
    double s = (m - 1.0) / (m + 1.0);
    double z = s * s;
    double q =      6.66666666666666666667e-02;
    q = fma(q, z, 7.69230769230769230769e-02);
    q = fma(q, z, 9.09090909090909090909e-02);
    q = fma(q, z, 1.11111111111111111111e-01);
    q = fma(q, z, 1.42857142857142857143e-01);
    q = fma(q, z, 2.00000000000000000000e-01);
    q = fma(q, z, 3.33333333333333333333e-01);
    double at = fma(s * z, q, s);
    return fma(2.0, at, kln);
}

__device__ __forceinline__ float sigmoid_f(float x) {
    return __fdiv_rn(1.0f, __fadd_rn(1.0f, __expf(-x)));
}

// ---------------------------------------------------------------------------
// k0: per-mode setup (round-9 form). Scalar input transforms: lanes 0-5 run
// one uniform branch-free double path; per-mode recurrence coeffs via short
// double polys.
// ---------------------------------------------------------------------------
__global__ void __launch_bounds__(128) k0_setup(
                         const float* __restrict__ mu_raw,
                         const float* __restrict__ D_raw,
                         const float* __restrict__ T0_raw,
                         const float* __restrict__ Ly_raw,
                         const float* __restrict__ xo_raw,
                         const float* __restrict__ yo_raw) {
    __shared__ float sc[6];
    int tid = threadIdx.x;
    if (tid < 6) {
        const float* p = (tid == 0) ? mu_raw : (tid == 1) ? D_raw :
                         (tid == 2) ? T0_raw : (tid == 3) ? Ly_raw :
                         (tid == 4) ? xo_raw : yo_raw;
        double x  = (double)*p;
        double ax = fabs(x);
        double sp = fmax(x, 0.0) + log1p_d(exp_d(-ax));
        double et = exp_d(-2.0 * ax);
        double th = (1.0 - et) / (1.0 + et);
        th = (x < 0.0) ? -th : th;
        float r = (tid < 3) ? __fadd_rn((float)sp, 1e-4f)
                            : __fmul_rn(__fadd_rn((float)th, 1.0f), 0.5f);
        sc[tid] = r;
    }
    __syncthreads();

    int m = blockIdx.x * blockDim.x + tid;
    if (m == 0) { g_maxbits = 0u; g_bar = 0u; }
    if (m >= NMODES) return;

    float mu = sc[0], Dm = sc[1], T0m = sc[2];
    float Ly = __fadd_rn(1.1f, __fmul_rn(2.9f, sc[3]));
    float xo = __fadd_rn(0.49f, __fmul_rn(0.51f, sc[4]));
    float hy = sc[5];
    float yo = __fadd_rn(__fmul_rn(0.51f, Ly), __fmul_rn(__fmul_rn(0.49f, Ly), hy));
    float yi = __fmul_rn(0.467f, Ly);

    int mi = m / MDIM + 1;
    int nj = m % MDIM + 1;
    const float PIf = (float)M_PI;

    float mf = (float)mi, nf = (float)nj;
    float t1 = __fmul_rn(mf, PIf);
    float t2 = __fdiv_rn(__fmul_rn(nf, PIf), Ly);
    float g1 = __fadd_rn(__fmul_rn(t1, t1), __fmul_rn(t2, t2));
    float om_sq = __fadd_rn(__fmul_rn(T0m, g1),
                            __fmul_rn(__fmul_rn(Dm, g1), g1));
    float omega = __fsqrt_rn(fmaxf(om_sq, 0.0f));
    float theta = __fmul_rn(omega, KF);

    const double OM2d   = 2.0 * M_PI * 500.0;
    const double DOMSQd = OM2d * OM2d;
    const double ALPHAd = 3.0 * log(10.0) / DOMSQd * (DOMSQd / 6.0);
    const double BETAd  = 3.0 * log(10.0) / DOMSQd * (1.0 / 2.0 - 1.0 / 6.0);
    float om2f  = __fmul_rn(omega, omega);
    float sigma = __fadd_rn((float)ALPHAd, __fmul_rn((float)BETAd, om2f));

    const float MAXOMf = (float)(10000.0 * 2.0 * M_PI);
    const float LOWOMf = (float)(20.0 * 2.0 * M_PI);
    float a1 = __fdiv_rn(__fsub_rn(MAXOMf, omega), 100.0f);
    float a2 = __fdiv_rn(__fsub_rn(omega, LOWOMf), 100.0f);
    float valid = __fmul_rn(sigmoid_f(a1), sigmoid_f(a2));

    const float XIPI = (float)(0.335 * M_PI);
    float inw = __fmul_rn(cos_accf(__fmul_rn(XIPI, mf)),
                          cos_accf(__fdiv_rn(__fmul_rn(__fmul_rn(yi, PIf), nf), Ly)));
    float outw = __fmul_rn(cos_accf(__fmul_rn(__fmul_rn(xo, PIf), mf)),
                           cos_accf(__fdiv_rn(__fmul_rn(__fmul_rn(yo, PIf), nf), Ly)));

    float ms = __fmul_rn(__fmul_rn(0.25f, mu), Ly);
    float E  = __expf(-__fmul_rn(sigma, KF));
    float P  = __fmul_rn(outw, inw);
    P = __fmul_rn(P, K2F);
    P = __fmul_rn(P, E);
    P = __fdiv_rn(P, ms);
    P = __fmul_rn(P, valid);

    float coef = __fdiv_rn(P, __fadd_rn(sin_acc(theta), 1e-8f));

    double Th32 = 32.0 * (double)theta;
    double c32d, s32d;
    sincos_d(Th32, s32d, c32d);
    double r32d = exp_d(-32.0 * (double)sigma * (1.0 / 44100.0));
    float  a    = (float)(2.0 * r32d * c32d);
    float  b    = (float)(-(r32d * r32d));
    float  z1c  = (float)(r32d * c32d);
    float  z1s  = (float)(r32d * s32d);

    double zr = r32d * c32d, zi = r32d * s32d;
#pragma unroll
    for (int k = 0; k < 4; ++k) {
        double nzr = zr * zr - zi * zi;
        double nzi = 2.0 * zr * zi;
        zr = nzr; zi = nzi;
    }
    float Z16c = (float)zr;
    float Z16s = (float)zi;

    g_P0[m] = make_float4(theta, sigma, coef, a);
    g_P1[m] = make_float4(b, z1c, z1s, Z16c);
    g_P2[m] = Z16s;
}

// ---------------------------------------------------------------------------
// k1: modal bank (round-4/9 form, at its FMA issue floor).
// ---------------------------------------------------------------------------
__global__ void __launch_bounds__(32 * WPB) k1_bank(int T) {
    int gtid   = blockIdx.x * blockDim.x + threadIdx.x;
    int warp_t = gtid >> 5;
    int lane   = threadIdx.x & 31;
    int base   = warp_t * SPAN + lane;
    if (base >= T) return;
    int c = blockIdx.y;

    float acc[TW];
#pragma unroll
    for (int j = 0; j < TW; ++j) acc[j] = 0.0f;

    float tp0 = (float)(base + 1);
    float nk0 = __fmul_rn((float)base, KF);

    int m0 = c * CHUNK;

    float4 nP0 = g_P0[m0];
    float4 nP1 = g_P1[m0];
    float  nP2 = g_P2[m0];

    for (int q = 0; q < CHUNK; ++q) {
        float4 p0 = nP0; float4 p1 = nP1; float p2 = nP2;
        if (q + 1 < CHUNK) {
            nP0 = g_P0[m0 + q + 1];
            nP1 = g_P1[m0 + q + 1];
            nP2 = g_P2[m0 + q + 1];
        }
        float th = p0.x, sg = p0.y, C = p0.z, a = p0.w;
        float b = p1.x, z1c = p1.y, z1s = p1.z, Z16c = p1.w, Z16s = p2;

        float s0, c0;
        sincos_acc(__fmul_rn(tp0, th), s0, c0);
        float E   = __fmul_rn(C, __expf(-__fmul_rn(sg, nk0)));
        float Wim = __fmul_rn(E, s0);
        float Wre = __fmul_rn(E, c0);

        float v0 = Wim;
        float v1 = __fmaf_rn(Wre, z1s, __fmul_rn(Wim, z1c));
        acc[0] = __fadd_rn(acc[0], v0);
        acc[1] = __fadd_rn(acc[1], v1);
#pragma unroll
        for (int j = 2; j < 16; ++j) {
            float v2 = __fmaf_rn(a, v1, __fmul_rn(b, v0));
            acc[j] = __fadd_rn(acc[j], v2);
            v0 = v1; v1 = v2;
        }

        float Wre2 = __fmaf_rn(Wre, Z16c, -__fmul_rn(Wim, Z16s));
        float Wim2 = __fmaf_rn(Wim, Z16c,  __fmul_rn(Wre, Z16s));
        v0 = Wim2;
        v1 = __fmaf_rn(Wre2, z1s, __fmul_rn(Wim2, z1c));
        acc[16] = __fadd_rn(acc[16], v0);
        acc[17] = __fadd_rn(acc[17], v1);
#pragma unroll
        for (int j = 18; j < TW; ++j) {
            float v2 = __fmaf_rn(a, v1, __fmul_rn(b, v0));
            acc[j] = __fadd_rn(acc[j], v2);
            v0 = v1; v1 = v2;
        }
    }

#pragma unroll
    for (int j = 0; j < TW; ++j) {
        int t = base + 32 * j;
        if (t < T) g_part[c][t] = acc[j];
    }
}

// ---------------------------------------------------------------------------
// k2: fused diff + max + normalize.
// Round-11 fix: block-level max reduction (shuffle + shared) -> ONE atomicMax
// per block (was: one per THREAD to a single address = ~19k serialized cycles).
// Boundary prev loaded in parallel by threads 0-63 (same ascending summation
// order as before -> ir bit-identical). Grid barrier as before (87 < 148).
// ---------------------------------------------------------------------------
__global__ void k2_fused(int T, float* __restrict__ out) {
    __shared__ float sm[257];
    __shared__ float sb[NCHUNK];
    __shared__ float smax[8];
    int t = blockIdx.x * blockDim.x + threadIdx.x;
    int lane = threadIdx.x & 31;
    int wid  = threadIdx.x >> 5;

    float s = 0.0f;
    if (t < T) {
#pragma unroll 16
        for (int c = 0; c < NCHUNK; ++c) s += g_part[c][t];
    }
    sm[threadIdx.x + 1] = s;

    // boundary prev: parallel-load the 64 chunk values of t-1
    int tp = (int)(blockIdx.x * blockDim.x) - 1;
    if (threadIdx.x < NCHUNK && tp >= 0 && tp < T)
        sb[threadIdx.x] = g_part[threadIdx.x][tp];
    __syncthreads();
    if (threadIdx.x == 0) {
        float p = 0.0f;
        if (tp >= 0 && tp < T) {
#pragma unroll
            for (int c = 0; c < NCHUNK; ++c) p += sb[c];   // ascending order
        }
        sm[0] = p;
    }
    __syncthreads();

    float ir = 0.0f;
    if (t < T) {
        float prev = (t == 0) ? 0.0f : sm[threadIdx.x];
        ir = __fdiv_rn(__fsub_rn(s, prev), KF);
    }

    // ---- block max reduction, then one atomicMax per block ----
    float mx = fabsf(ir);
#pragma unroll
    for (int off = 16; off > 0; off >>= 1)
        mx = fmaxf(mx, __shfl_xor_sync(0xffffffffu, mx, off));
    if (lane == 0) smax[wid] = mx;
    __syncthreads();
    if (threadIdx.x == 0) {
        float bm = smax[0];
#pragma unroll
        for (int w = 1; w < 8; ++w) bm = fmaxf(bm, smax[w]);
        atomicMax(&g_maxbits, __float_as_uint(bm));
    }

    // ---- grid barrier ----
    __threadfence();
    __syncthreads();
    if (threadIdx.x == 0) {
        atomicAdd(&g_bar, 1u);
        while (*(volatile unsigned*)&g_bar < gridDim.x) {
            __nanosleep(64);
        }
    }
    __syncthreads();
    __threadfence();

    if (t < T) {
        float gmx = __uint_as_float(*(volatile unsigned*)&g_maxbits);
        out[t] = __fdiv_rn(ir, __fadd_rn(gmx, 1e-8f));
    }
}

// ---------------------------------------------------------------------------
extern "C" void kernel_launch(void* const* d_in, const int* in_sizes, int n_in,
                              void* d_out, int out_size) {
    (void)in_sizes; (void)n_in;
    const float* mu   = (const float*)d_in[0];
    const float* Dr   = (const float*)d_in[1];
    const float* T0r  = (const float*)d_in[2];
    const float* Lyr  = (const float*)d_in[3];
    const float* xor_ = (const float*)d_in[4];
    const float* yor_ = (const float*)d_in[5];

    int T = out_size;
    if (T > MAX_T) T = MAX_T;

    k0_setup<<<NMODES / 128, 128>>>(mu, Dr, T0r, Lyr, xor_, yor_);

    int warps_t  = (T + SPAN - 1) / SPAN;
    int blocks_x = (warps_t + WPB - 1) / WPB;
    dim3 g1(blocks_x, NCHUNK);
    k1_bank<<<g1, 32 * WPB>>>(T);

    int gb = (T + 255) / 256;
    k2_fused<<<gb, 256>>>(T, (float*)d_out);
}

// round 12
// speedup vs baseline: 1.1231x; 1.0818x over previous
#include <cuda_runtime.h>
#include <math.h>

#define NMODES   6400
#define MDIM     80
#define NCHUNK   64
#define CHUNK    (NMODES / NCHUNK)      /* 100 modes per chunk */
#define MAX_T    24576
#define TW       32                      /* samples per thread, stride 32 */
#define SPAN     1024                    /* samples per warp tile */
#define WPB      4                       /* warps per block in k1 */
#define K2SAMP   255                     /* samples per k2 block (256 pairs - 1 halo) */

#define KF   ((float)(1.0 / 44100.0))
#define K2F  ((float)((1.0/44100.0)*(1.0/44100.0)))

// per-mode tables
__device__ float4   g_P0[NMODES];   // {theta, sigma, C, a}
__device__ float4   g_P1[NMODES];   // {b, z1c, z1s, Z16c}
__device__ float    g_P2[NMODES];   // {Z16s}
__device__ float    g_part[NCHUNK][MAX_T];
__device__ unsigned g_maxbits;
__device__ unsigned g_bar;

// ---------------------------------------------------------------------------
// Accurate flag-proof float sine / sincos / cosine (Cody-Waite, minimax).
// ---------------------------------------------------------------------------
__device__ __forceinline__ float sin_acc(float x) {
    const float INV_PI = 0.318309886183790671538f;
    float nf = rintf(__fmul_rn(x, INV_PI));
    int   ni = (int)nf;
    float r = __fmaf_rn(-nf, 3.140625f, x);
    r = __fmaf_rn(-nf, 9.670257568359375e-4f, r);
    r = __fmaf_rn(-nf, 6.2771141529083252e-7f, r);
    float r2 = __fmul_rn(r, r);
    float p  = __fmaf_rn(2.60831598097865935e-06f, r2, -1.98106907191686332e-4f);
    p = __fmaf_rn(p, r2,  8.33307858556509018e-3f);
    p = __fmaf_rn(p, r2, -0.166666597127914429f);
    float s = __fmaf_rn(__fmul_rn(r, r2), p, r);
    return __int_as_float(__float_as_int(s) ^ ((ni & 1) << 31));
}

__device__ __forceinline__ void sincos_acc(float x, float& so, float& co) {
    const float INV_PI = 0.318309886183790671538f;
    float nf = rintf(__fmul_rn(x, INV_PI));
    int   sgn = ((int)nf & 1) << 31;
    float r = __fmaf_rn(-nf, 3.140625f, x);
    r = __fmaf_rn(-nf, 9.670257568359375e-4f, r);
    r = __fmaf_rn(-nf, 6.2771141529083252e-7f, r);
    float r2 = __fmul_rn(r, r);
    float ps = __fmaf_rn(2.60831598097865935e-06f, r2, -1.98106907191686332e-4f);
    ps = __fmaf_rn(ps, r2,  8.33307858556509018e-3f);
    ps = __fmaf_rn(ps, r2, -0.166666597127914429f);
    float s = __fmaf_rn(__fmul_rn(r, r2), ps, r);
    float pc = __fmaf_rn(2.44331571e-5f, r2, -1.38873162e-3f);
    pc = __fmaf_rn(pc, r2, 4.16666456e-2f);
    pc = __fmaf_rn(pc, r2, -0.5f);
    float c = __fmaf_rn(pc, r2, 1.0f);
    so = __int_as_float(__float_as_int(s) ^ sgn);
    co = __int_as_float(__float_as_int(c) ^ sgn);
}

// cos(x) for amplitude path, |x| < ~400
__device__ __forceinline__ float cos_accf(float x) {
    const float INV_PI = 0.318309886183790671538f;
    float nf = rintf(__fmaf_rn(x, INV_PI, -0.5f));
    int   ni = (int)nf;
    float nh = __fadd_rn(nf, 0.5f);
    float r = __fmaf_rn(-nh, 3.140625f, x);
    r = __fmaf_rn(-nh, 9.670257568359375e-4f, r);
    r = __fmaf_rn(-nh, 6.2771141529083252e-7f, r);
    r = __fmaf_rn(-nh, 1.2154201256553420e-10f, r);
    float r2 = __fmul_rn(r, r);
    float p  = __fmaf_rn(2.60831598097865935e-06f, r2, -1.98106907191686332e-4f);
    p = __fmaf_rn(p, r2,  8.33307858556509018e-3f);
    p = __fmaf_rn(p, r2, -0.166666597127914429f);
    float s = __fmaf_rn(__fmul_rn(r, r2), p, r);
    return __int_as_float(__float_as_int(s) ^ ((~ni & 1) << 31));
}

// ---------------------------------------------------------------------------
// Short custom double transcendentals (branch-free, known small ranges).
// ---------------------------------------------------------------------------
__device__ __forceinline__ void sincos_d(double x, double& so, double& co) {
    double n = rint(x * 0.31830988618379067154);
    double r = fma(-n, 3.14159265358979311600, x);
    double y = r * r;
    double ps =        1.58969099521155010221e-10;
    ps = fma(ps, y, -2.50507602534068634195e-08);
    ps = fma(ps, y,  2.75573137070700676789e-06);
    ps = fma(ps, y, -1.98412698298579493134e-04);
    ps = fma(ps, y,  8.33333333332248946124e-03);
    ps = fma(ps, y, -1.66666666666666324348e-01);
    double s = fma(r * y, ps, r);
    double pc =       -1.13596475577881948265e-11;
    pc = fma(pc, y,  2.08757232129817482790e-09);
    pc = fma(pc, y, -2.75573143513906633035e-07);
    pc = fma(pc, y,  2.48015872894767294178e-05);
    pc = fma(pc, y, -1.38888888888741095749e-03);
    pc = fma(pc, y,  4.16666666666666019037e-02);
    double c = fma(y * y, pc, fma(y, -0.5, 1.0));
    long long ni = (long long)n;
    if (ni & 1) { s = -s; c = -c; }
    so = s; co = c;
}

// exp(v), v in [-745, 0]; branch-free (clamp guards the scale only)
__device__ __forceinline__ double exp_d(double v) {
    double vc = fmax(v, -700.0);
    double kd = rint(vc * 1.44269504088896340736);
    double r = fma(-kd, 6.93147180369123816490e-01, vc);
    r = fma(-kd, 1.90821492927058770002e-10, r);
    double p =       2.50521083854417187751e-08;
    p = fma(p, r, 2.75573192239858906526e-07);
    p = fma(p, r, 2.75573192239858925110e-06);
    p = fma(p, r, 2.48015873015873015873e-05);
    p = fma(p, r, 1.98412698412698412526e-04);
    p = fma(p, r, 1.38888888888888894069e-03);
    p = fma(p, r, 8.33333333333333321769e-03);
    p = fma(p, r, 4.16666666666666666435e-02);
    p = fma(p, r, 1.66666666666666666666e-01);
    p = fma(p, r, 5.00000000000000000000e-01);
    p = fma(p, r, 1.0);
    p = fma(p, r, 1.0);
    long long ki = (long long)kd;
    double two_k = __longlong_as_double((1023LL + ki) << 52);
    return p * two_k;
}

// log1p(e) for e in (0, 1]; branch-free select reduction + atanh series.
__device__ __forceinline__ double log1p_d(double e) {
    double w = 1.0 + e;
    bool   big = w > 1.4142135623730951;
    double m   = big ? 0.5 * w : w;
    double kln = big ? 6.93147180559945309417e-01 : 0.0;
    double s = (m - 1.0) / (m + 1.0);
    double z = s * s;
    double q =      6.66666666666666666667e-02;
    q = fma(q, z, 7.69230769230769230769e-02);
    q = fma(q, z, 9.09090909090909090909e-02);
    q = fma(q, z, 1.11111111111111111111e-01);
    q = fma(q, z, 1.42857142857142857143e-01);
    q = fma(q, z, 2.00000000000000000000e-01);
    q = fma(q, z, 3.33333333333333333333e-01);
    double at = fma(s * z, q, s);
    return fma(2.0, at, kln);
}

__device__ __forceinline__ float sigmoid_f(float x) {
    return __fdiv_rn(1.0f, __fadd_rn(1.0f, __expf(-x)));
}

// ---------------------------------------------------------------------------
// k0: per-mode setup (round-9 form, frozen this round).
// ---------------------------------------------------------------------------
__global__ void __launch_bounds__(128) k0_setup(
                         const float* __restrict__ mu_raw,
                         const float* __restrict__ D_raw,
                         const float* __restrict__ T0_raw,
                         const float* __restrict__ Ly_raw,
                         const float* __restrict__ xo_raw,
                         const float* __restrict__ yo_raw) {
    __shared__ float sc[6];
    int tid = threadIdx.x;
    if (tid < 6) {
        const float* p = (tid == 0) ? mu_raw : (tid == 1) ? D_raw :
                         (tid == 2) ? T0_raw : (tid == 3) ? Ly_raw :
                         (tid == 4) ? xo_raw : yo_raw;
        double x  = (double)*p;
        double ax = fabs(x);
        double sp = fmax(x, 0.0) + log1p_d(exp_d(-ax));
        double et = exp_d(-2.0 * ax);
        double th = (1.0 - et) / (1.0 + et);
        th = (x < 0.0) ? -th : th;
        float r = (tid < 3) ? __fadd_rn((float)sp, 1e-4f)
                            : __fmul_rn(__fadd_rn((float)th, 1.0f), 0.5f);
        sc[tid] = r;
    }
    __syncthreads();

    int m = blockIdx.x * blockDim.x + tid;
    if (m == 0) { g_maxbits = 0u; g_bar = 0u; }
    if (m >= NMODES) return;

    float mu = sc[0], Dm = sc[1], T0m = sc[2];
    float Ly = __fadd_rn(1.1f, __fmul_rn(2.9f, sc[3]));
    float xo = __fadd_rn(0.49f, __fmul_rn(0.51f, sc[4]));
    float hy = sc[5];
    float yo = __fadd_rn(__fmul_rn(0.51f, Ly), __fmul_rn(__fmul_rn(0.49f, Ly), hy));
    float yi = __fmul_rn(0.467f, Ly);

    int mi = m / MDIM + 1;
    int nj = m % MDIM + 1;
    const float PIf = (float)M_PI;

    float mf = (float)mi, nf = (float)nj;
    float t1 = __fmul_rn(mf, PIf);
    float t2 = __fdiv_rn(__fmul_rn(nf, PIf), Ly);
    float g1 = __fadd_rn(__fmul_rn(t1, t1), __fmul_rn(t2, t2));
    float om_sq = __fadd_rn(__fmul_rn(T0m, g1),
                            __fmul_rn(__fmul_rn(Dm, g1), g1));
    float omega = __fsqrt_rn(fmaxf(om_sq, 0.0f));
    float theta = __fmul_rn(omega, KF);

    const double OM2d   = 2.0 * M_PI * 500.0;
    const double DOMSQd = OM2d * OM2d;
    const double ALPHAd = 3.0 * log(10.0) / DOMSQd * (DOMSQd / 6.0);
    const double BETAd  = 3.0 * log(10.0) / DOMSQd * (1.0 / 2.0 - 1.0 / 6.0);
    float om2f  = __fmul_rn(omega, omega);
    float sigma = __fadd_rn((float)ALPHAd, __fmul_rn((float)BETAd, om2f));

    const float MAXOMf = (float)(10000.0 * 2.0 * M_PI);
    const float LOWOMf = (float)(20.0 * 2.0 * M_PI);
    float a1 = __fdiv_rn(__fsub_rn(MAXOMf, omega), 100.0f);
    float a2 = __fdiv_rn(__fsub_rn(omega, LOWOMf), 100.0f);
    float valid = __fmul_rn(sigmoid_f(a1), sigmoid_f(a2));

    const float XIPI = (float)(0.335 * M_PI);
    float inw = __fmul_rn(cos_accf(__fmul_rn(XIPI, mf)),
                          cos_accf(__fdiv_rn(__fmul_rn(__fmul_rn(yi, PIf), nf), Ly)));
    float outw = __fmul_rn(cos_accf(__fmul_rn(__fmul_rn(xo, PIf), mf)),
                           cos_accf(__fdiv_rn(__fmul_rn(__fmul_rn(yo, PIf), nf), Ly)));

    float ms = __fmul_rn(__fmul_rn(0.25f, mu), Ly);
    float E  = __expf(-__fmul_rn(sigma, KF));
    float P  = __fmul_rn(outw, inw);
    P = __fmul_rn(P, K2F);
    P = __fmul_rn(P, E);
    P = __fdiv_rn(P, ms);
    P = __fmul_rn(P, valid);

    float coef = __fdiv_rn(P, __fadd_rn(sin_acc(theta), 1e-8f));

    double Th32 = 32.0 * (double)theta;
    double c32d, s32d;
    sincos_d(Th32, s32d, c32d);
    double r32d = exp_d(-32.0 * (double)sigma * (1.0 / 44100.0));
    float  a    = (float)(2.0 * r32d * c32d);
    float  b    = (float)(-(r32d * r32d));
    float  z1c  = (float)(r32d * c32d);
    float  z1s  = (float)(r32d * s32d);

    double zr = r32d * c32d, zi = r32d * s32d;
#pragma unroll
    for (int k = 0; k < 4; ++k) {
        double nzr = zr * zr - zi * zi;
        double nzi = 2.0 * zr * zi;
        zr = nzr; zi = nzi;
    }
    float Z16c = (float)zr;
    float Z16s = (float)zi;

    g_P0[m] = make_float4(theta, sigma, coef, a);
    g_P1[m] = make_float4(b, z1c, z1s, Z16c);
    g_P2[m] = Z16s;
}

// ---------------------------------------------------------------------------
// k1: modal bank. Round-12 change: the two 14-step half-tile recurrence
// chains are INDEPENDENT (second starts from W*Z16, known at init) — run
// them interleaved for 2x ILP in the 8-cycle dependence window. Identical
// FP ops in identical per-element order -> bit-identical output.
// ---------------------------------------------------------------------------
__global__ void __launch_bounds__(32 * WPB) k1_bank(int T) {
    int gtid   = blockIdx.x * blockDim.x + threadIdx.x;
    int warp_t = gtid >> 5;
    int lane   = threadIdx.x & 31;
    int base   = warp_t * SPAN + lane;
    if (base >= T) return;
    int c = blockIdx.y;

    float acc[TW];
#pragma unroll
    for (int j = 0; j < TW; ++j) acc[j] = 0.0f;

    float tp0 = (float)(base + 1);
    float nk0 = __fmul_rn((float)base, KF);

    int m0 = c * CHUNK;

    float4 nP0 = g_P0[m0];
    float4 nP1 = g_P1[m0];
    float  nP2 = g_P2[m0];

    for (int q = 0; q < CHUNK; ++q) {
        float4 p0 = nP0; float4 p1 = nP1; float p2 = nP2;
        if (q + 1 < CHUNK) {
            nP0 = g_P0[m0 + q + 1];
            nP1 = g_P1[m0 + q + 1];
            nP2 = g_P2[m0 + q + 1];
        }
        float th = p0.x, sg = p0.y, C = p0.z, a = p0.w;
        float b = p1.x, z1c = p1.y, z1s = p1.z, Z16c = p1.w, Z16s = p2;

        // ---- init: one accurate sincos + envelope; resync rotation upfront ----
        float s0, c0;
        sincos_acc(__fmul_rn(tp0, th), s0, c0);
        float E   = __fmul_rn(C, __expf(-__fmul_rn(sg, nk0)));
        float Wim = __fmul_rn(E, s0);
        float Wre = __fmul_rn(E, c0);
        float Wre2 = __fmaf_rn(Wre, Z16c, -__fmul_rn(Wim, Z16s));
        float Wim2 = __fmaf_rn(Wim, Z16c,  __fmul_rn(Wre, Z16s));

        float v0a = Wim;
        float v1a = __fmaf_rn(Wre, z1s, __fmul_rn(Wim, z1c));
        float v0b = Wim2;
        float v1b = __fmaf_rn(Wre2, z1s, __fmul_rn(Wim2, z1c));
        acc[0]  = __fadd_rn(acc[0],  v0a);
        acc[1]  = __fadd_rn(acc[1],  v1a);
        acc[16] = __fadd_rn(acc[16], v0b);
        acc[17] = __fadd_rn(acc[17], v1b);
#pragma unroll
        for (int j = 2; j < 16; ++j) {
            float v2a = __fmaf_rn(a, v1a, __fmul_rn(b, v0a));
            float v2b = __fmaf_rn(a, v1b, __fmul_rn(b, v0b));
            acc[j]      = __fadd_rn(acc[j],      v2a);
            acc[j + 16] = __fadd_rn(acc[j + 16], v2b);
            v0a = v1a; v1a = v2a;
            v0b = v1b; v1b = v2b;
        }
    }

#pragma unroll
    for (int j = 0; j < TW; ++j) {
        int t = base + 32 * j;
        if (t < T) g_part[c][t] = acc[j];
    }
}

// ---------------------------------------------------------------------------
// k2: fused diff + max + normalize, parallelism-first layout.
// 512 threads = 256 pairs; pair p sums sample (base + p - 1): even thread
// sums chunks 0-31, odd sums 32-63, combined via shfl. Pair 0 is the halo
// (provides prev for the block's first output sample). 87 blocks of 512
// threads — all co-resident (grid barrier safe).
// ---------------------------------------------------------------------------
__global__ void __launch_bounds__(512) k2_fused(int T, float* __restrict__ out) {
    __shared__ float ssum[256];
    __shared__ float smax[16];
    int tid  = threadIdx.x;
    int pair = tid >> 1;
    int half = tid & 1;
    int lane = tid & 31;
    int wid  = tid >> 5;

    int base = blockIdx.x * K2SAMP;      // pair p -> sample base + p - 1
    int t    = base + pair - 1;

    float s = 0.0f;
    if (t >= 0 && t < T) {
        int c0 = half * 32;
#pragma unroll 8
        for (int c = 0; c < 32; ++c) s += g_part[c0 + c][t];
    }
    float so = __shfl_down_sync(0xffffffffu, s, 1);
    if (half == 0) ssum[pair] = __fadd_rn(s, so);
    __syncthreads();

    float ir = 0.0f;
    bool  valid = (half == 0) && (pair >= 1) && (t < T);
    if (valid) {
        // t >= 0 here; at t==0 ssum[pair-1] is the guarded halo sum == 0
        float prev = ssum[pair - 1];
        ir = __fdiv_rn(__fsub_rn(ssum[pair], prev), KF);
    }

    // ---- block max reduction, one atomicMax per block ----
    float mx = valid ? fabsf(ir) : 0.0f;
#pragma unroll
    for (int off = 16; off > 0; off >>= 1)
        mx = fmaxf(mx, __shfl_xor_sync(0xffffffffu, mx, off));
    if (lane == 0) smax[wid] = mx;
    __syncthreads();
    if (tid == 0) {
        float bm = smax[0];
#pragma unroll
        for (int w = 1; w < 16; ++w) bm = fmaxf(bm, smax[w]);
        atomicMax(&g_maxbits, __float_as_uint(bm));
    }

    // ---- grid barrier ----
    __threadfence();
    __syncthreads();
    if (tid == 0) {
        atomicAdd(&g_bar, 1u);
        while (*(volatile unsigned*)&g_bar < gridDim.x) {
            __nanosleep(64);
        }
    }
    __syncthreads();
    __threadfence();

    if (valid) {
        float gmx = __uint_as_float(*(volatile unsigned*)&g_maxbits);
        out[t] = __fdiv_rn(ir, __fadd_rn(gmx, 1e-8f));
    }
}

// ---------------------------------------------------------------------------
extern "C" void kernel_launch(void* const* d_in, const int* in_sizes, int n_in,
                              void* d_out, int out_size) {
    (void)in_sizes; (void)n_in;
    const float* mu   = (const float*)d_in[0];
    const float* Dr   = (const float*)d_in[1];
    const float* T0r  = (const float*)d_in[2];
    const float* Lyr  = (const float*)d_in[3];
    const float* xor_ = (const float*)d_in[4];
    const float* yor_ = (const float*)d_in[5];

    int T = out_size;
    if (T > MAX_T) T = MAX_T;

    k0_setup<<<NMODES / 128, 128>>>(mu, Dr, T0r, Lyr, xor_, yor_);

    int warps_t  = (T + SPAN - 1) / SPAN;
    int blocks_x = (warps_t + WPB - 1) / WPB;
    dim3 g1(blocks_x, NCHUNK);
    k1_bank<<<g1, 32 * WPB>>>(T);

    int gb = (T + K2SAMP - 1) / K2SAMP;
    k2_fused<<<gb, 512>>>(T, (float*)d_out);
}